// round 1
// baseline (speedup 1.0000x reference)
#include <cuda_runtime.h>

#define NN 8192
#define DD 512
#define LOGIT_SCALE 2.659f
#define BM 128
#define BN 128
#define BK 32

// Scratch (allocation-free rule: __device__ globals)
__device__ float g_imgN[NN * DD];
__device__ float g_txtN[NN * DD];
__device__ float g_stats[4 * NN];   // [Zimg | Ztxt | Wimg | Wtxt]
__device__ int   g_lab64;           // 1 if labels buffer is int64 laid out as int32 pairs

// ---------------- packed fp32x2 helpers (sm_100+ FFMA2) ----------------
__device__ __forceinline__ unsigned long long pack2(float lo, float hi) {
    unsigned long long r;
    asm("mov.b64 %0, {%1, %2};" : "=l"(r) : "f"(lo), "f"(hi));
    return r;
}
__device__ __forceinline__ void ffma2(unsigned long long &d, unsigned long long a, unsigned long long b) {
    asm("fma.rn.f32x2 %0, %1, %2, %0;" : "+l"(d) : "l"(a), "l"(b));
}
__device__ __forceinline__ float2 unpack2(unsigned long long v) {
    float2 r;
    asm("mov.b64 {%0, %1}, %2;" : "=f"(r.x), "=f"(r.y) : "l"(v));
    return r;
}

__device__ __forceinline__ int get_label(const int* __restrict__ labels, int i) {
    return g_lab64 ? labels[2 * i] : labels[i];
}

// ---------------- labels dtype sniffer ----------------
// If labels are int64 (values in [-1, 99]), every odd int32 word is the sign
// extension of the even word. For int32 labels that pattern is (astronomically)
// impossible across 4096 pairs. Reads only the first 8192 int32 words, which is
// in-bounds for both layouts.
__global__ void detect_labels_kernel(const int* __restrict__ labels) {
    __shared__ int bad;
    if (threadIdx.x == 0) bad = 0;
    __syncthreads();
    int mybad = 0;
    for (int i = threadIdx.x; i < NN / 2; i += blockDim.x) {
        int lo = labels[2 * i];
        int hi = labels[2 * i + 1];
        if (hi != (lo < 0 ? -1 : 0)) mybad = 1;
    }
    if (mybad) bad = 1;
    __syncthreads();
    if (threadIdx.x == 0) g_lab64 = (bad == 0) ? 1 : 0;
}

// ---------------- normalize + zero stats ----------------
// grid (NN, 2), block 128.  y==0: image -> g_imgN,  y==1: text -> g_txtN
__global__ void prep_kernel(const float* __restrict__ txt, const float* __restrict__ img) {
    const int row = blockIdx.x;
    const int t = threadIdx.x;
    const float* __restrict__ src = blockIdx.y ? txt : img;
    float* __restrict__ dst = blockIdx.y ? g_txtN : g_imgN;

    if (blockIdx.y == 0 && t < 4) g_stats[row * 4 + t] = 0.0f;

    float4 v = reinterpret_cast<const float4*>(src)[row * (DD / 4) + t];
    float ss = v.x * v.x + v.y * v.y + v.z * v.z + v.w * v.w;
#pragma unroll
    for (int m = 16; m; m >>= 1) ss += __shfl_xor_sync(0xffffffffu, ss, m);
    __shared__ float sm[4];
    if ((t & 31) == 0) sm[t >> 5] = ss;
    __syncthreads();
    float tot = sm[0] + sm[1] + sm[2] + sm[3];
    float inv = 1.0f / fmaxf(sqrtf(tot), 1e-12f);
    float4 o = make_float4(v.x * inv, v.y * inv, v.z * inv, v.w * inv);
    reinterpret_cast<float4*>(dst)[row * (DD / 4) + t] = o;
}

// ---------------- fused GEMM + exp/mask statistics ----------------
// grid (NN/BN, NN/BM), block 256 (16x16 threads, 8x8 microtile each).
// Accumulates, for its 128x128 tile of S = scale * imgN @ txtN^T:
//   Zimg[i] += sum_j exp(S_ij)   Ztxt[j] += sum_i exp(S_ij)
//   Wimg[i] += sum_j T_ij S_ij   Wtxt[j] += sum_i T_ij S_ij
__global__ __launch_bounds__(256) void gemm_stats_kernel(const int* __restrict__ labels) {
    __shared__ float As[BK][BM];
    __shared__ float Bs[BK][BN];
    __shared__ int labI[BM];
    __shared__ int labJ[BN];

    const int tid = threadIdx.x;
    const int tx = tid & 15;
    const int ty = tid >> 4;
    const int lane = tid & 31;
    const int iBase = blockIdx.y * BM;
    const int jBase = blockIdx.x * BN;

    if (tid < 128) labI[tid] = get_label(labels, iBase + tid);
    else           labJ[tid - 128] = get_label(labels, jBase + tid - 128);

    const float4* A4 = reinterpret_cast<const float4*>(g_imgN);
    const float4* B4 = reinterpret_cast<const float4*>(g_txtN);

    unsigned long long acc[8][4];
#pragma unroll
    for (int r = 0; r < 8; r++)
#pragma unroll
        for (int j = 0; j < 4; j++) acc[r][j] = 0ull;

    for (int kc = 0; kc < DD; kc += BK) {
        __syncthreads();
#pragma unroll
        for (int p = 0; p < 4; p++) {
            int idx = tid + p * 256;
            int row = idx >> 3;      // 0..127
            int q = idx & 7;         // float4 within the 32-wide k chunk
            float4 va = A4[(iBase + row) * (DD / 4) + (kc >> 2) + q];
            As[q * 4 + 0][row] = va.x;
            As[q * 4 + 1][row] = va.y;
            As[q * 4 + 2][row] = va.z;
            As[q * 4 + 3][row] = va.w;
            float4 vb = B4[(jBase + row) * (DD / 4) + (kc >> 2) + q];
            Bs[q * 4 + 0][row] = vb.x;
            Bs[q * 4 + 1][row] = vb.y;
            Bs[q * 4 + 2][row] = vb.z;
            Bs[q * 4 + 3][row] = vb.w;
        }
        __syncthreads();
#pragma unroll
        for (int k = 0; k < BK; k++) {
            float4 a0 = *reinterpret_cast<const float4*>(&As[k][ty * 8]);
            float4 a1 = *reinterpret_cast<const float4*>(&As[k][ty * 8 + 4]);
            float4 b0 = *reinterpret_cast<const float4*>(&Bs[k][tx * 8]);
            float4 b1 = *reinterpret_cast<const float4*>(&Bs[k][tx * 8 + 4]);
            unsigned long long bp0 = pack2(b0.x, b0.y);
            unsigned long long bp1 = pack2(b0.z, b0.w);
            unsigned long long bp2 = pack2(b1.x, b1.y);
            unsigned long long bp3 = pack2(b1.z, b1.w);
            float av[8] = {a0.x, a0.y, a0.z, a0.w, a1.x, a1.y, a1.z, a1.w};
#pragma unroll
            for (int r = 0; r < 8; r++) {
                unsigned long long ap = pack2(av[r], av[r]);
                ffma2(acc[r][0], ap, bp0);
                ffma2(acc[r][1], ap, bp1);
                ffma2(acc[r][2], ap, bp2);
                ffma2(acc[r][3], ap, bp3);
            }
        }
    }

    // ---- epilogue: exp / mask / reduce ----
    float colZ[8], colW[8];
#pragma unroll
    for (int c = 0; c < 8; c++) { colZ[c] = 0.f; colW[c] = 0.f; }

#pragma unroll
    for (int r = 0; r < 8; r++) {
        int row = ty * 8 + r;
        int gi = iBase + row;
        int li = labI[row];
        float rZ = 0.f, rW = 0.f;
#pragma unroll
        for (int j = 0; j < 4; j++) {
            float2 p = unpack2(acc[r][j]);
#pragma unroll
            for (int h = 0; h < 2; h++) {
                int c = j * 2 + h;
                int col = tx * 8 + c;
                int gj = jBase + col;
                float s = LOGIT_SCALE * (h ? p.y : p.x);
                float e = __expf(s);
                rZ += e;
                colZ[c] += e;
                int lj = labJ[col];
                bool tmask = (gi == gj) || ((li == lj) && (li != -1));
                if (tmask) { rW += s; colW[c] += s; }
            }
        }
        // reduce row partials across the 16 tx lanes (xor 8..1 stays in 16-group)
#pragma unroll
        for (int m = 8; m; m >>= 1) {
            rZ += __shfl_xor_sync(0xffffffffu, rZ, m);
            rW += __shfl_xor_sync(0xffffffffu, rW, m);
        }
        if (tx == 0) {
            atomicAdd(&g_stats[gi], rZ);              // Zimg
            atomicAdd(&g_stats[2 * NN + gi], rW);     // Wimg
        }
    }
    // column partials: combine the two ty-halves of the warp (same tx -> same cols)
#pragma unroll
    for (int c = 0; c < 8; c++) {
        colZ[c] += __shfl_xor_sync(0xffffffffu, colZ[c], 16);
        colW[c] += __shfl_xor_sync(0xffffffffu, colW[c], 16);
    }
    if (lane < 16) {
#pragma unroll
        for (int c = 0; c < 8; c++) {
            int gj = jBase + tx * 8 + c;
            atomicAdd(&g_stats[NN + gj], colZ[c]);        // Ztxt
            atomicAdd(&g_stats[3 * NN + gj], colW[c]);    // Wtxt
        }
    }
}

// ---------------- final reduction -> scalar loss ----------------
__global__ void reduce_kernel(const int* __restrict__ labels, float* __restrict__ out) {
    __shared__ int cnt[100];
    __shared__ float red[32];
    const int t = threadIdx.x;
    if (t < 100) cnt[t] = 0;
    __syncthreads();
    for (int i = t; i < NN; i += blockDim.x) {
        int l = get_label(labels, i);
        if (l >= 0) atomicAdd(&cnt[l], 1);
    }
    __syncthreads();
    float acc = 0.f;
    for (int i = t; i < NN; i += blockDim.x) {
        int l = get_label(labels, i);
        float C = (l >= 0) ? (float)cnt[l] : 1.0f;
        float invC = 1.0f / C;
        acc += logf(g_stats[i])      - g_stats[2 * NN + i] * invC;   // image side
        acc += logf(g_stats[NN + i]) - g_stats[3 * NN + i] * invC;   // text side
    }
#pragma unroll
    for (int m = 16; m; m >>= 1) acc += __shfl_xor_sync(0xffffffffu, acc, m);
    if ((t & 31) == 0) red[t >> 5] = acc;
    __syncthreads();
    if (t < 32) {
        float v = (t < (int)(blockDim.x >> 5)) ? red[t] : 0.f;
#pragma unroll
        for (int m = 16; m; m >>= 1) v += __shfl_xor_sync(0xffffffffu, v, m);
        if (t == 0) out[0] = v / (2.0f * NN);
    }
}

extern "C" void kernel_launch(void* const* d_in, const int* in_sizes, int n_in,
                              void* d_out, int out_size) {
    const float* txt = (const float*)d_in[0];   // text_features
    const float* img = (const float*)d_in[1];   // image_features
    const int* labels = (const int*)d_in[2];    // labels (int32 or int64 — sniffed)

    detect_labels_kernel<<<1, 256>>>(labels);
    prep_kernel<<<dim3(NN, 2), 128>>>(txt, img);
    gemm_stats_kernel<<<dim3(NN / BN, NN / BM), 256>>>(labels);
    reduce_kernel<<<1, 1024>>>(labels, (float*)d_out);
}

// round 5
// speedup vs baseline: 6.7576x; 6.7576x over previous
#include <cuda_runtime.h>
#include <cuda_bf16.h>
#include <stdint.h>

#define NN 8192
#define DD 512
#define LOGIT_SCALE 2.659f
#define BM 128
#define BN 128
#define BK 32
#define NITER (DD / BK)

// ---- scratch (__device__ globals; no allocations allowed) ----
__device__ __nv_bfloat16 g_imgH[NN * DD];
__device__ __nv_bfloat16 g_txtH[NN * DD];
__device__ float g_stats[4 * NN];   // [Zimg | Ztxt | Wimg | Wtxt]
__device__ int   g_lab64;

// =============== helpers ===============
__device__ __forceinline__ uint32_t smem_u32(const void* p) {
    uint32_t a;
    asm("{ .reg .u64 t; cvta.to.shared.u64 t, %1; cvt.u32.u64 %0, t; }" : "=r"(a) : "l"(p));
    return a;
}
__device__ __forceinline__ void cp_async16(uint32_t s, const void* g) {
    uint64_t gg;
    asm("cvta.to.global.u64 %0, %1;" : "=l"(gg) : "l"(g));
    asm volatile("cp.async.cg.shared.global [%0], [%1], 16;" :: "r"(s), "l"(gg) : "memory");
}
#define CP_COMMIT() asm volatile("cp.async.commit_group;" ::: "memory")
#define CP_WAIT(n)  asm volatile("cp.async.wait_group %0;" :: "n"(n) : "memory")

__device__ __forceinline__ void ldsm_x4(uint32_t* r, uint32_t addr) {
    asm volatile("ldmatrix.sync.aligned.m8n8.x4.shared.b16 {%0,%1,%2,%3}, [%4];"
                 : "=r"(r[0]), "=r"(r[1]), "=r"(r[2]), "=r"(r[3]) : "r"(addr));
}
__device__ __forceinline__ void mma_bf16(float* d, const uint32_t* a, uint32_t b0, uint32_t b1) {
    asm volatile("mma.sync.aligned.m16n8k16.row.col.f32.bf16.bf16.f32 "
                 "{%0,%1,%2,%3}, {%4,%5,%6,%7}, {%8,%9}, {%0,%1,%2,%3};"
                 : "+f"(d[0]), "+f"(d[1]), "+f"(d[2]), "+f"(d[3])
                 : "r"(a[0]), "r"(a[1]), "r"(a[2]), "r"(a[3]), "r"(b0), "r"(b1));
}

// swizzled byte offset inside a [128 rows x 64B] stage
__device__ __forceinline__ uint32_t sw_off(int row, int ch) {
    return (uint32_t)(row * 4 + (ch ^ ((row >> 1) & 3))) * 16u;
}

__device__ __forceinline__ int get_label(const int* __restrict__ labels, int i) {
    return g_lab64 ? labels[2 * i] : labels[i];
}

// ---------------- labels dtype sniffer (int64 vs int32) ----------------
__global__ void detect_labels_kernel(const int* __restrict__ labels) {
    __shared__ int bad;
    if (threadIdx.x == 0) bad = 0;
    __syncthreads();
    int mybad = 0;
    for (int i = threadIdx.x; i < NN / 2; i += blockDim.x) {
        int lo = labels[2 * i];
        int hi = labels[2 * i + 1];
        if (hi != (lo < 0 ? -1 : 0)) mybad = 1;
    }
    if (mybad) bad = 1;
    __syncthreads();
    if (threadIdx.x == 0) g_lab64 = (bad == 0) ? 1 : 0;
}

// ---------------- normalize + fp32->bf16 + zero stats ----------------
__global__ void prep_kernel(const float* __restrict__ txt, const float* __restrict__ img) {
    const int row = blockIdx.x;
    const int t = threadIdx.x;
    const float* __restrict__ src = blockIdx.y ? txt : img;
    __nv_bfloat16* __restrict__ dst = blockIdx.y ? g_txtH : g_imgH;

    if (blockIdx.y == 0 && t < 4) g_stats[row * 4 + t] = 0.0f;

    float4 v = reinterpret_cast<const float4*>(src)[row * (DD / 4) + t];
    float ss = v.x * v.x + v.y * v.y + v.z * v.z + v.w * v.w;
#pragma unroll
    for (int m = 16; m; m >>= 1) ss += __shfl_xor_sync(0xffffffffu, ss, m);
    __shared__ float sm[4];
    if ((t & 31) == 0) sm[t >> 5] = ss;
    __syncthreads();
    float tot = sm[0] + sm[1] + sm[2] + sm[3];
    float inv = 1.0f / fmaxf(sqrtf(tot), 1e-12f);
    __nv_bfloat162 a = __floats2bfloat162_rn(v.x * inv, v.y * inv);
    __nv_bfloat162 b = __floats2bfloat162_rn(v.z * inv, v.w * inv);
    uint2 o = make_uint2(*reinterpret_cast<uint32_t*>(&a), *reinterpret_cast<uint32_t*>(&b));
    reinterpret_cast<uint2*>(dst)[row * (DD / 4) + t] = o;
}

// ---------------- HMMA GEMM + fused exp/mask statistics ----------------
// grid (64, 64), 256 threads (8 warps = 4M x 2N, warp tile 32x64).
__global__ __launch_bounds__(256) void gemm_mma_kernel(const int* __restrict__ labels) {
    __shared__ __align__(128) char As[2][BM * 64];   // 2 x 8KB (128 rows x 64B)
    __shared__ __align__(128) char Bs[2][BN * 64];
    __shared__ int labI[BM], labJ[BN];
    __shared__ float smRowZ[BM], smRowW[BM], smColZ[BN], smColW[BN];

    const int tid = threadIdx.x;
    const int wid = tid >> 5;
    const int lane = tid & 31;
    const int warpM = wid & 3;
    const int warpN = wid >> 2;
    const int iBase = blockIdx.y * BM;
    const int jBase = blockIdx.x * BN;

    if (tid < BM) {
        smRowZ[tid] = 0.f; smRowW[tid] = 0.f;
        smColZ[tid] = 0.f; smColW[tid] = 0.f;
        labI[tid] = get_label(labels, iBase + tid);
        labJ[tid] = get_label(labels, jBase + tid);
    }

    const __nv_bfloat16* __restrict__ gA = g_imgH;
    const __nv_bfloat16* __restrict__ gB = g_txtH;
    const uint32_t aS[2] = { smem_u32(As[0]), smem_u32(As[1]) };
    const uint32_t bS[2] = { smem_u32(Bs[0]), smem_u32(Bs[1]) };

    // prologue: load stage 0
    {
        const int kc = 0;
#pragma unroll
        for (int p = 0; p < 2; p++) {
            int idx = tid + p * 256;
            int row = idx >> 2, ch = idx & 3;
            uint32_t so = sw_off(row, ch);
            cp_async16(aS[0] + so, gA + (size_t)(iBase + row) * DD + kc + ch * 8);
            cp_async16(bS[0] + so, gB + (size_t)(jBase + row) * DD + kc + ch * 8);
        }
        CP_COMMIT();
    }

    float acc[2][8][4];
#pragma unroll
    for (int mt = 0; mt < 2; mt++)
#pragma unroll
        for (int nt = 0; nt < 8; nt++)
#pragma unroll
            for (int f = 0; f < 4; f++) acc[mt][nt][f] = 0.f;

    __syncthreads();   // covers labI/labJ + stats init too

    for (int it = 0; it < NITER; it++) {
        if (it + 1 < NITER) {
            const int kc = (it + 1) * BK;
            const int buf = (it + 1) & 1;
#pragma unroll
            for (int p = 0; p < 2; p++) {
                int idx = tid + p * 256;
                int row = idx >> 2, ch = idx & 3;
                uint32_t so = sw_off(row, ch);
                cp_async16(aS[buf] + so, gA + (size_t)(iBase + row) * DD + kc + ch * 8);
                cp_async16(bS[buf] + so, gB + (size_t)(jBase + row) * DD + kc + ch * 8);
            }
            CP_COMMIT();
            CP_WAIT(1);
        } else {
            CP_WAIT(0);
        }
        __syncthreads();

        const int buf = it & 1;
#pragma unroll
        for (int ks = 0; ks < 2; ks++) {
            uint32_t a[2][4], b[4][4];
            const int lrow = lane & 15;
            const int lch = ks * 2 + (lane >> 4);
#pragma unroll
            for (int mt = 0; mt < 2; mt++) {
                int row = warpM * 32 + mt * 16 + lrow;
                ldsm_x4(a[mt], aS[buf] + sw_off(row, lch));
            }
#pragma unroll
            for (int n2 = 0; n2 < 4; n2++) {
                int row = warpN * 64 + n2 * 16 + lrow;
                ldsm_x4(b[n2], bS[buf] + sw_off(row, lch));
            }
#pragma unroll
            for (int mt = 0; mt < 2; mt++)
#pragma unroll
                for (int nt = 0; nt < 8; nt++)
                    mma_bf16(acc[mt][nt], a[mt], b[nt >> 1][nt & 1], b[nt >> 1][(nt & 1) + 2]);
        }
        __syncthreads();
    }

    // ---- fused epilogue ----
    const int g = lane >> 2;
    const int tc = (lane & 3) * 2;

    int li[2][2], gi[2][2], lj[8][2], gj[8][2];
#pragma unroll
    for (int mt = 0; mt < 2; mt++)
#pragma unroll
        for (int i = 0; i < 2; i++) {
            int r = warpM * 32 + mt * 16 + g + i * 8;
            gi[mt][i] = iBase + r;
            li[mt][i] = labI[r];
        }
#pragma unroll
    for (int nt = 0; nt < 8; nt++)
#pragma unroll
        for (int c = 0; c < 2; c++) {
            int cl = warpN * 64 + nt * 8 + tc + c;
            gj[nt][c] = cl;
            lj[nt][c] = labJ[cl];
        }

    float rowZ[2][2] = {}, rowW[2][2] = {}, colZ[8][2] = {};
#pragma unroll
    for (int mt = 0; mt < 2; mt++)
#pragma unroll
        for (int nt = 0; nt < 8; nt++)
#pragma unroll
            for (int f = 0; f < 4; f++) {
                int i = f >> 1, c = f & 1;
                float s = LOGIT_SCALE * acc[mt][nt][f];
                float e = __expf(s);
                rowZ[mt][i] += e;
                colZ[nt][c] += e;
                bool msk = (gi[mt][i] == jBase + gj[nt][c]) ||
                           ((li[mt][i] == lj[nt][c]) && (li[mt][i] != -1));
                if (msk) { rowW[mt][i] += s; atomicAdd(&smColW[gj[nt][c]], s); }
            }

    // row reduce across lanes sharing groupID (xor 1, 2)
#pragma unroll
    for (int mt = 0; mt < 2; mt++)
#pragma unroll
        for (int i = 0; i < 2; i++) {
#pragma unroll
            for (int m = 1; m <= 2; m <<= 1) {
                rowZ[mt][i] += __shfl_xor_sync(0xffffffffu, rowZ[mt][i], m);
                rowW[mt][i] += __shfl_xor_sync(0xffffffffu, rowW[mt][i], m);
            }
            if ((lane & 3) == 0) {
                int r = warpM * 32 + mt * 16 + g + i * 8;
                atomicAdd(&smRowZ[r], rowZ[mt][i]);
                atomicAdd(&smRowW[r], rowW[mt][i]);
            }
        }
    // col reduce across lane groups (xor 4, 8, 16)
#pragma unroll
    for (int nt = 0; nt < 8; nt++)
#pragma unroll
        for (int c = 0; c < 2; c++) {
#pragma unroll
            for (int m = 4; m <= 16; m <<= 1)
                colZ[nt][c] += __shfl_xor_sync(0xffffffffu, colZ[nt][c], m);
            if (lane < 4) atomicAdd(&smColZ[gj[nt][c]], colZ[nt][c]);
        }
    __syncthreads();

    if (tid < BM) {
        atomicAdd(&g_stats[iBase + tid],          smRowZ[tid]);
        atomicAdd(&g_stats[2 * NN + iBase + tid], smRowW[tid]);
        atomicAdd(&g_stats[NN + jBase + tid],     smColZ[tid]);
        atomicAdd(&g_stats[3 * NN + jBase + tid], smColW[tid]);
    }
}

// ---------------- final reduction -> scalar loss ----------------
__global__ void reduce_kernel(const int* __restrict__ labels, float* __restrict__ out) {
    __shared__ int cnt[100];
    __shared__ float red[32];
    const int t = threadIdx.x;
    if (t < 100) cnt[t] = 0;
    __syncthreads();
    for (int i = t; i < NN; i += blockDim.x) {
        int l = get_label(labels, i);
        if (l >= 0) atomicAdd(&cnt[l], 1);
    }
    __syncthreads();
    float acc = 0.f;
    for (int i = t; i < NN; i += blockDim.x) {
        int l = get_label(labels, i);
        float invC = (l >= 0) ? (1.0f / (float)cnt[l]) : 1.0f;
        acc += logf(g_stats[i])      - g_stats[2 * NN + i] * invC;
        acc += logf(g_stats[NN + i]) - g_stats[3 * NN + i] * invC;
    }
#pragma unroll
    for (int m = 16; m; m >>= 1) acc += __shfl_xor_sync(0xffffffffu, acc, m);
    if ((t & 31) == 0) red[t >> 5] = acc;
    __syncthreads();
    if (t < 32) {
        float v = (t < (int)(blockDim.x >> 5)) ? red[t] : 0.f;
#pragma unroll
        for (int m = 16; m; m >>= 1) v += __shfl_xor_sync(0xffffffffu, v, m);
        if (t == 0) out[0] = v / (2.0f * NN);
    }
}

extern "C" void kernel_launch(void* const* d_in, const int* in_sizes, int n_in,
                              void* d_out, int out_size) {
    const float* txt = (const float*)d_in[0];
    const float* img = (const float*)d_in[1];
    const int* labels = (const int*)d_in[2];

    detect_labels_kernel<<<1, 256>>>(labels);
    prep_kernel<<<dim3(NN, 2), 128>>>(txt, img);
    gemm_mma_kernel<<<dim3(NN / BN, NN / BM), 256>>>(labels);
    reduce_kernel<<<1, 1024>>>(labels, (float*)d_out);
}

// round 6
// speedup vs baseline: 6.8518x; 1.0139x over previous
#include <cuda_runtime.h>
#include <cuda_bf16.h>
#include <stdint.h>

#define NN 8192
#define DD 512
#define LOGIT_SCALE 2.659f
#define FSCALE 32.0f                       // feature pre-scale before e4m3 quantization
#define SC (LOGIT_SCALE / (FSCALE * FSCALE))
#define BM 128
#define BN 128
#define BK 64                              // fp8 elems per k-chunk (64 B/row)
#define NITER (DD / BK)                    // 8
#define NSTAGE 3

// ---- scratch (__device__ globals; no allocations allowed) ----
__device__ uint8_t g_imgQ[NN * DD];        // e4m3, pre-scaled by FSCALE
__device__ uint8_t g_txtQ[NN * DD];
__device__ float g_stats[4 * NN];          // [Zimg | Ztxt | Wimg | Wtxt]
__device__ int   g_lab64;

// =============== helpers ===============
__device__ __forceinline__ uint32_t smem_u32(const void* p) {
    uint32_t a;
    asm("{ .reg .u64 t; cvta.to.shared.u64 t, %1; cvt.u32.u64 %0, t; }" : "=r"(a) : "l"(p));
    return a;
}
__device__ __forceinline__ void cp_async16(uint32_t s, const void* g) {
    uint64_t gg;
    asm("cvta.to.global.u64 %0, %1;" : "=l"(gg) : "l"(g));
    asm volatile("cp.async.cg.shared.global [%0], [%1], 16;" :: "r"(s), "l"(gg) : "memory");
}
#define CP_COMMIT() asm volatile("cp.async.commit_group;" ::: "memory")
#define CP_WAIT(n)  asm volatile("cp.async.wait_group %0;" :: "n"(n) : "memory")

__device__ __forceinline__ void ldsm_x4(uint32_t* r, uint32_t addr) {
    asm volatile("ldmatrix.sync.aligned.m8n8.x4.shared.b16 {%0,%1,%2,%3}, [%4];"
                 : "=r"(r[0]), "=r"(r[1]), "=r"(r[2]), "=r"(r[3]) : "r"(addr));
}
// fp8 e4m3 MMA, m16n8k32, fp32 accumulate (sm_89+ baseline feature)
__device__ __forceinline__ void mma_fp8(float* d, const uint32_t* a, uint32_t b0, uint32_t b1) {
    asm volatile("mma.sync.aligned.m16n8k32.row.col.f32.e4m3.e4m3.f32 "
                 "{%0,%1,%2,%3}, {%4,%5,%6,%7}, {%8,%9}, {%0,%1,%2,%3};"
                 : "+f"(d[0]), "+f"(d[1]), "+f"(d[2]), "+f"(d[3])
                 : "r"(a[0]), "r"(a[1]), "r"(a[2]), "r"(a[3]), "r"(b0), "r"(b1));
}
__device__ __forceinline__ uint16_t pack_e4m3x2(float lo, float hi) {
    uint16_t r;
    asm("cvt.rn.satfinite.e4m3x2.f32 %0, %2, %1;" : "=h"(r) : "f"(lo), "f"(hi));
    return r;
}

// swizzled byte offset inside a [128 rows x 64B] stage (4 x 16B chunks per row)
__device__ __forceinline__ uint32_t sw_off(int row, int ch) {
    return (uint32_t)(row * 4 + (ch ^ ((row >> 1) & 3))) * 16u;
}

__device__ __forceinline__ int get_label(const int* __restrict__ labels, int i) {
    return g_lab64 ? labels[2 * i] : labels[i];
}

// ---------------- labels dtype sniffer (int64 vs int32) ----------------
__global__ void detect_labels_kernel(const int* __restrict__ labels) {
    __shared__ int bad;
    if (threadIdx.x == 0) bad = 0;
    __syncthreads();
    int mybad = 0;
    for (int i = threadIdx.x; i < NN / 2; i += blockDim.x) {
        int lo = labels[2 * i];
        int hi = labels[2 * i + 1];
        if (hi != (lo < 0 ? -1 : 0)) mybad = 1;
    }
    if (mybad) bad = 1;
    __syncthreads();
    if (threadIdx.x == 0) g_lab64 = (bad == 0) ? 1 : 0;
}

// ---------------- normalize + fp32 -> e4m3(x32) + zero stats ----------------
__global__ void prep_kernel(const float* __restrict__ txt, const float* __restrict__ img) {
    const int row = blockIdx.x;
    const int t = threadIdx.x;
    const float* __restrict__ src = blockIdx.y ? txt : img;
    uint8_t* __restrict__ dst = blockIdx.y ? g_txtQ : g_imgQ;

    if (blockIdx.y == 0 && t < 4) g_stats[row * 4 + t] = 0.0f;

    float4 v = reinterpret_cast<const float4*>(src)[row * (DD / 4) + t];
    float ss = v.x * v.x + v.y * v.y + v.z * v.z + v.w * v.w;
#pragma unroll
    for (int m = 16; m; m >>= 1) ss += __shfl_xor_sync(0xffffffffu, ss, m);
    __shared__ float sm[4];
    if ((t & 31) == 0) sm[t >> 5] = ss;
    __syncthreads();
    float tot = sm[0] + sm[1] + sm[2] + sm[3];
    float inv = FSCALE / fmaxf(sqrtf(tot), 1e-12f);
    uint16_t lo = pack_e4m3x2(v.x * inv, v.y * inv);
    uint16_t hi = pack_e4m3x2(v.z * inv, v.w * inv);
    reinterpret_cast<uint32_t*>(dst)[row * (DD / 4) + t] = (uint32_t)lo | ((uint32_t)hi << 16);
}

// ---------------- FP8 QMMA GEMM + fused exp/mask statistics ----------------
// grid (64, 64), 256 threads (8 warps = 4M x 2N, warp tile 32x64).
__global__ __launch_bounds__(256, 2) void gemm_mma_kernel(const int* __restrict__ labels) {
    __shared__ __align__(128) char As[NSTAGE][BM * 64];   // 3 x 8KB
    __shared__ __align__(128) char Bs[NSTAGE][BN * 64];
    __shared__ int labI[BM], labJ[BN];
    __shared__ float smRowZ[BM], smRowW[BM], smColZ[BN], smColW[BN];

    const int tid = threadIdx.x;
    const int wid = tid >> 5;
    const int lane = tid & 31;
    const int warpM = wid & 3;
    const int warpN = wid >> 2;
    const int iBase = blockIdx.y * BM;
    const int jBase = blockIdx.x * BN;

    if (tid < BM) {
        smRowZ[tid] = 0.f; smRowW[tid] = 0.f;
        smColZ[tid] = 0.f; smColW[tid] = 0.f;
        labI[tid] = get_label(labels, iBase + tid);
        labJ[tid] = get_label(labels, jBase + tid);
    }

    const uint8_t* __restrict__ gA = g_imgQ;
    const uint8_t* __restrict__ gB = g_txtQ;
    uint32_t aS[NSTAGE], bS[NSTAGE];
#pragma unroll
    for (int s = 0; s < NSTAGE; s++) { aS[s] = smem_u32(As[s]); bS[s] = smem_u32(Bs[s]); }

    // prologue: issue stages 0 and 1
#pragma unroll
    for (int pre = 0; pre < 2; pre++) {
        const int kc = pre * BK;
#pragma unroll
        for (int p = 0; p < 2; p++) {
            int idx = tid + p * 256;
            int row = idx >> 2, ch = idx & 3;
            uint32_t so = sw_off(row, ch);
            cp_async16(aS[pre] + so, gA + (size_t)(iBase + row) * DD + kc + ch * 16);
            cp_async16(bS[pre] + so, gB + (size_t)(jBase + row) * DD + kc + ch * 16);
        }
        CP_COMMIT();
    }

    float acc[2][8][4];
#pragma unroll
    for (int mt = 0; mt < 2; mt++)
#pragma unroll
        for (int nt = 0; nt < 8; nt++)
#pragma unroll
            for (int f = 0; f < 4; f++) acc[mt][nt][f] = 0.f;

    for (int it = 0; it < NITER; it++) {
        CP_WAIT(1);          // stage `it` complete (≤1 pending = it+1)
        __syncthreads();     // all warps see stage it; all done reading stage (it-1)%3's buffer

        if (it + 2 < NITER) {
            const int kc = (it + 2) * BK;
            const int buf = (it + 2) % NSTAGE;
#pragma unroll
            for (int p = 0; p < 2; p++) {
                int idx = tid + p * 256;
                int row = idx >> 2, ch = idx & 3;
                uint32_t so = sw_off(row, ch);
                cp_async16(aS[buf] + so, gA + (size_t)(iBase + row) * DD + kc + ch * 16);
                cp_async16(bS[buf] + so, gB + (size_t)(jBase + row) * DD + kc + ch * 16);
            }
        }
        CP_COMMIT();         // commit (possibly empty) group to keep wait counts aligned

        const int buf = it % NSTAGE;
#pragma unroll
        for (int ks = 0; ks < 2; ks++) {   // two k=32 steps per 64B chunk
            uint32_t a[2][4], b[4][4];
            const int lrow = lane & 15;
            const int lch = ks * 2 + (lane >> 4);
#pragma unroll
            for (int mt = 0; mt < 2; mt++) {
                int row = warpM * 32 + mt * 16 + lrow;
                ldsm_x4(a[mt], aS[buf] + sw_off(row, lch));
            }
#pragma unroll
            for (int n2 = 0; n2 < 4; n2++) {
                int row = warpN * 64 + n2 * 16 + lrow;
                ldsm_x4(b[n2], bS[buf] + sw_off(row, lch));
            }
#pragma unroll
            for (int mt = 0; mt < 2; mt++)
#pragma unroll
                for (int nt = 0; nt < 8; nt++)
                    mma_fp8(acc[mt][nt], a[mt], b[nt >> 1][nt & 1], b[nt >> 1][(nt & 1) + 2]);
        }
    }
    __syncthreads();

    // ---- fused epilogue ----
    const int g = lane >> 2;
    const int tc = (lane & 3) * 2;

    int li[2][2], gi[2][2], lj[8][2], gj[8][2];
#pragma unroll
    for (int mt = 0; mt < 2; mt++)
#pragma unroll
        for (int i = 0; i < 2; i++) {
            int r = warpM * 32 + mt * 16 + g + i * 8;
            gi[mt][i] = iBase + r;
            li[mt][i] = labI[r];
        }
#pragma unroll
    for (int nt = 0; nt < 8; nt++)
#pragma unroll
        for (int c = 0; c < 2; c++) {
            int cl = warpN * 64 + nt * 8 + tc + c;
            gj[nt][c] = cl;
            lj[nt][c] = labJ[cl];
        }

    float rowZ[2][2] = {}, rowW[2][2] = {}, colZ[8][2] = {};
#pragma unroll
    for (int mt = 0; mt < 2; mt++)
#pragma unroll
        for (int nt = 0; nt < 8; nt++)
#pragma unroll
            for (int f = 0; f < 4; f++) {
                int i = f >> 1, c = f & 1;
                float s = SC * acc[mt][nt][f];
                float e = __expf(s);
                rowZ[mt][i] += e;
                colZ[nt][c] += e;
                bool msk = (gi[mt][i] == jBase + gj[nt][c]) ||
                           ((li[mt][i] == lj[nt][c]) && (li[mt][i] != -1));
                if (msk) { rowW[mt][i] += s; atomicAdd(&smColW[gj[nt][c]], s); }
            }

#pragma unroll
    for (int mt = 0; mt < 2; mt++)
#pragma unroll
        for (int i = 0; i < 2; i++) {
#pragma unroll
            for (int m = 1; m <= 2; m <<= 1) {
                rowZ[mt][i] += __shfl_xor_sync(0xffffffffu, rowZ[mt][i], m);
                rowW[mt][i] += __shfl_xor_sync(0xffffffffu, rowW[mt][i], m);
            }
            if ((lane & 3) == 0) {
                int r = warpM * 32 + mt * 16 + g + i * 8;
                atomicAdd(&smRowZ[r], rowZ[mt][i]);
                atomicAdd(&smRowW[r], rowW[mt][i]);
            }
        }
#pragma unroll
    for (int nt = 0; nt < 8; nt++)
#pragma unroll
        for (int c = 0; c < 2; c++) {
#pragma unroll
            for (int m = 4; m <= 16; m <<= 1)
                colZ[nt][c] += __shfl_xor_sync(0xffffffffu, colZ[nt][c], m);
            if (lane < 4) atomicAdd(&smColZ[gj[nt][c]], colZ[nt][c]);
        }
    __syncthreads();

    if (tid < BM) {
        atomicAdd(&g_stats[iBase + tid],          smRowZ[tid]);
        atomicAdd(&g_stats[2 * NN + iBase + tid], smRowW[tid]);
        atomicAdd(&g_stats[NN + jBase + tid],     smColZ[tid]);
        atomicAdd(&g_stats[3 * NN + jBase + tid], smColW[tid]);
    }
}

// ---------------- final reduction -> scalar loss ----------------
__global__ void reduce_kernel(const int* __restrict__ labels, float* __restrict__ out) {
    __shared__ int cnt[100];
    __shared__ float red[32];
    const int t = threadIdx.x;
    if (t < 100) cnt[t] = 0;
    __syncthreads();
    for (int i = t; i < NN; i += blockDim.x) {
        int l = get_label(labels, i);
        if (l >= 0) atomicAdd(&cnt[l], 1);
    }
    __syncthreads();
    float acc = 0.f;
    for (int i = t; i < NN; i += blockDim.x) {
        int l = get_label(labels, i);
        float invC = (l >= 0) ? (1.0f / (float)cnt[l]) : 1.0f;
        acc += __logf(g_stats[i])      - g_stats[2 * NN + i] * invC;
        acc += __logf(g_stats[NN + i]) - g_stats[3 * NN + i] * invC;
    }
#pragma unroll
    for (int m = 16; m; m >>= 1) acc += __shfl_xor_sync(0xffffffffu, acc, m);
    if ((t & 31) == 0) red[t >> 5] = acc;
    __syncthreads();
    if (t < 32) {
        float v = (t < (int)(blockDim.x >> 5)) ? red[t] : 0.f;
#pragma unroll
        for (int m = 16; m; m >>= 1) v += __shfl_xor_sync(0xffffffffu, v, m);
        if (t == 0) out[0] = v / (2.0f * NN);
    }
}

extern "C" void kernel_launch(void* const* d_in, const int* in_sizes, int n_in,
                              void* d_out, int out_size) {
    const float* txt = (const float*)d_in[0];
    const float* img = (const float*)d_in[1];
    const int* labels = (const int*)d_in[2];

    detect_labels_kernel<<<1, 256>>>(labels);
    prep_kernel<<<dim3(NN, 2), 128>>>(txt, img);
    gemm_mma_kernel<<<dim3(NN / BN, NN / BM), 256>>>(labels);
    reduce_kernel<<<1, 1024>>>(labels, (float*)d_out);
}